// round 5
// baseline (speedup 1.0000x reference)
#include <cuda_runtime.h>
#include <math.h>
#include <stdint.h>

// Problem dims
#define T_DIM 4096
#define B_DIM 512
#define NSTEP 4095
#define NSTEP_PAD 4104             // padded: 6-deep prefetch ring needs no guards
#define NELEM (T_DIM * B_DIM)      // 2,097,152
#define PREP_BLOCKS (NELEM / 256)  // 8192
#define PLANE ((size_t)NSTEP_PAD * B_DIM)   // float4 elements per plane

// ---------------------------------------------------------------------------
// Plane-major packed coefficients: 5 planes of [step][b] float4 (coalesced).
//   plane0 = (C1, C3, C2, C4)
//   plane1 = (A,  mn, mx, label)
//   plane2 = (Cd', kThz, kThd1, kThd2)
//   plane3 = (e1, e2, -u1, u2)
//   plane4 = (e3, -kTo', 0, 0)
// ---------------------------------------------------------------------------
__device__ float4 g_pack[5 * PLANE]; // ~168 MB
__device__ double g_part[PREP_BLOCKS];
__device__ float  g_hover;
__device__ double g_loss[B_DIM];

// ---------------------------------------------------------------------------
// f32x2 packed helpers (sm_100a)
// ---------------------------------------------------------------------------
union F2U { float2 f; unsigned long long u; };

__device__ __forceinline__ float2 mul2(float2 a, float2 b) {
    F2U A, B, R; A.f = a; B.f = b;
    asm("mul.rn.f32x2 %0, %1, %2;" : "=l"(R.u) : "l"(A.u), "l"(B.u));
    return R.f;
}
__device__ __forceinline__ float2 add2(float2 a, float2 b) {
    F2U A, B, R; A.f = a; B.f = b;
    asm("add.rn.f32x2 %0, %1, %2;" : "=l"(R.u) : "l"(A.u), "l"(B.u));
    return R.f;
}
__device__ __forceinline__ float2 fma2(float2 a, float2 b, float2 c) {
    F2U A, B, C, R; A.f = a; B.f = b; C.f = c;
    asm("fma.rn.f32x2 %0, %1, %2, %3;" : "=l"(R.u) : "l"(A.u), "l"(B.u), "l"(C.u));
    return R.f;
}
// exact packed subtraction: a - b == fma(b, -1, a)
__device__ __forceinline__ float2 sub2(float2 a, float2 b) {
    return fma2(b, make_float2(-1.0f, -1.0f), a);
}

__device__ __forceinline__ float sc(float g, float base) {
    float t = (0.5f - g) * 95.0f;
    t = t / 100.0f;
    return (1.0f + t) * base;
}

// ---------------------------------------------------------------------------
// Kernel 1: precompute folded coefficients + partial sums of kTh (for hover)
// ---------------------------------------------------------------------------
__global__ void __launch_bounds__(256) prep_kernel(
    const float* __restrict__ logits,
    const float* __restrict__ u1p, const float* __restrict__ u2p,
    const float* __restrict__ u3p, const float* __restrict__ u4p,
    const float* __restrict__ maxp, const float* __restrict__ minp,
    const float* __restrict__ lab)
{
    const int idx = blockIdx.x * 256 + threadIdx.x;
    const float4* lg = reinterpret_cast<const float4*>(logits) + (size_t)idx * 3;
    float4 l0 = lg[0];
    float4 l1 = lg[1];
    float4 l2 = lg[2];

    float kTh = sc(l1.w, 1.076e-05f);

    __shared__ double red[256];
    red[threadIdx.x] = (double)kTh;
    __syncthreads();
    #pragma unroll
    for (int s = 128; s > 0; s >>= 1) {
        if (threadIdx.x < s) red[threadIdx.x] += red[threadIdx.x + s];
        __syncthreads();
    }
    if (threadIdx.x == 0) g_part[blockIdx.x] = red[0];

    const int t = idx >> 9;
    const int b = idx & 511;
    if (t >= 1) {
        const float tau = 0.005f;
        const float TM  = (float)(0.005 / 1.2);   // tau / mB
        const float UPT = (float)(1e-4 * 0.005);  // uP*IRzz*tau

        float dxm  = sc(l0.x, 0.16f);
        float dym  = sc(l0.y, 0.16f);
        float IBxx = sc(l0.w, 0.0123f);
        float IByy = sc(l1.x, 0.0123f);
        float IBzz = sc(l1.y, 0.0123f);
        float Cd   = sc(l1.z, 0.1f);
        float kTo  = sc(l2.x, 1.632e-07f);
        float tau2 = sc(l2.y, 0.015f);
        float kp   = sc(l2.z, 1.0f);
        float damp = sc(l2.w, 1.0f);

        float A   = (-2.0f * damp) * tau2;
        float t2s = tau2 * tau2;
        float C1 = (kp * u1p[idx]) / t2s;
        float C2 = (kp * u2p[idx]) / t2s;
        float C3 = (kp * u3p[idx]) / t2s;
        float C4 = (kp * u4p[idx]) / t2s;

        float Cdz   = Cd * TM;
        float kThz  = kTh * TM;
        float kThd1 = ((kTh * dym) * tau) / IBxx;
        float kThd2 = ((kTh * dxm) * tau) / IByy;
        float e1 = ((IByy - IBzz) * tau) / IBxx;
        float u1 = UPT / IBxx;
        float e2 = ((IBzz - IBxx) * tau) / IByy;
        float u2 = UPT / IByy;
        float e3 = ((IBxx - IByy) * tau) / IBzz;
        float kToz = (kTo * tau) / IBzz;

        size_t o = (size_t)(t - 1) * B_DIM + b;
        g_pack[0 * PLANE + o] = make_float4(C1, C3, C2, C4);
        g_pack[1 * PLANE + o] = make_float4(A, minp[idx], maxp[idx], lab[idx]);
        g_pack[2 * PLANE + o] = make_float4(Cdz, kThz, kThd1, kThd2);
        g_pack[3 * PLANE + o] = make_float4(e1, e2, -u1, u2);
        g_pack[4 * PLANE + o] = make_float4(e3, -kToz, 0.f, 0.f);
    }
}

// ---------------------------------------------------------------------------
// Kernel 2: hover = sqrt(max(mB*g/(4*mean(kTh)+eps), 1e-6))
// ---------------------------------------------------------------------------
__global__ void hover_kernel()
{
    __shared__ double red[256];
    double s = 0.0;
    for (int i = threadIdx.x; i < PREP_BLOCKS; i += 256) s += g_part[i];
    red[threadIdx.x] = s;
    __syncthreads();
    #pragma unroll
    for (int st = 128; st > 0; st >>= 1) {
        if (threadIdx.x < st) red[threadIdx.x] += red[threadIdx.x + st];
        __syncthreads();
    }
    if (threadIdx.x == 0) {
        float m   = (float)(red[0] / (double)NELEM);
        float den = 4.0f * m + 1e-12f;
        float v   = (float)(1.2 * 9.81) / den;
        v = fmaxf(v, 1e-6f);
        g_hover = sqrtf(v);
    }
}

// ---------------------------------------------------------------------------
// Kernel 3: serial simulation. 16 blocks x 32 threads, 1 thread/trajectory.
// f32x2-packed, division-free inner loop; plane-major coalesced loads;
// 6-deep register prefetch ring.
// ---------------------------------------------------------------------------
__global__ void __launch_bounds__(32, 1) sim_kernel(const float* __restrict__ labels)
{
    const int b = blockIdx.x * 32 + threadIdx.x;
    const float tau = 0.005f;
    const float HT  = 0.0025f;   // tau * 0.5
    const float GT  = 0.04905f;  // g * tau

    const float2 TAUD = make_float2(tau,  tau);
    const float2 HTmp = make_float2(-HT,  HT);
    const float2 HTpm = make_float2( HT, -HT);
    const float2 HTn2 = make_float2(-HT, -HT);
    const float2 HTp2 = make_float2( HT,  HT);

    const float hover = g_hover;

    float xz = 0.f;
    float q0 = 1.f, q1 = 0.f, q2 = 0.f, q3 = 0.f;
    float zd = 0.f, pv = 0.f, qv = 0.f, rv = 0.f;
    float2 Wa = make_float2(hover, hover);
    float2 Wb = make_float2(hover, hover);
    float2 Da = make_float2(0.f, 0.f);
    float2 Db = make_float2(0.f, 0.f);

    double acc;
    { float l0 = labels[b]; acc = (double)l0 * (double)l0; }

    // per-plane base pointers for this lane (coalesced across the warp)
    const float4* __restrict__ P0 = g_pack + 0 * PLANE + b;
    const float4* __restrict__ P1 = g_pack + 1 * PLANE + b;
    const float4* __restrict__ P2 = g_pack + 2 * PLANE + b;
    const float4* __restrict__ P3 = g_pack + 3 * PLANE + b;
    const float4* __restrict__ P4 = g_pack + 4 * PLANE + b;

    float4 buf[6][5];
    #pragma unroll
    for (int j = 0; j < 6; ++j) {
        const size_t o = (size_t)j * B_DIM;
        buf[j][0] = P0[o]; buf[j][1] = P1[o]; buf[j][2] = P2[o];
        buf[j][3] = P3[o]; buf[j][4] = P4[o];
    }

    float accf = 0.f;

    auto step = [&](const float4 p0, const float4 p1, const float4 p2,
                    const float4 p3, const float4 p4) {
        const float2 C13 = make_float2(p0.x, p0.y);
        const float2 C24 = make_float2(p0.z, p0.w);
        const float2 A2  = make_float2(p1.x, p1.x);
        const float mn = p1.y, mx = p1.z, lbl = p1.w;
        const float Cdz = p2.x, kThz = p2.y;
        const float2 K  = make_float2(p2.z, p2.w);   // (kThd1, kThd2)
        const float2 E  = make_float2(p3.x, p3.y);   // (e1, e2)
        const float2 U  = make_float2(p3.z, p3.w);   // (-u1, u2)
        const float e3 = p4.x, nkToz = p4.y;

        // motor accelerations: (A*wd + C) - w
        float2 wddA = sub2(fma2(A2, Da, C13), Wa);
        float2 wddB = sub2(fma2(A2, Db, C24), Wb);

        // clip (FMNMX, alu pipe)
        float2 WaC = make_float2(fminf(fmaxf(Wa.x, mn), mx),
                                 fminf(fmaxf(Wa.y, mn), mx));
        float2 WbC = make_float2(fminf(fmaxf(Wb.x, mn), mx),
                                 fminf(fmaxf(Wb.y, mn), mx));

        float2 Sa = mul2(WaC, WaC);   // (s1, s3)
        float2 Sb = mul2(WbC, WbC);   // (s2, s4)
        float2 aP = add2(Sa, Sb);     // (a12, a34)
        float2 dP = sub2(Sa, Sb);     // (d12, d34)
        float sa  = aP.x + aP.y;
        float spp = aP.x - aP.y;
        float smm = dP.x - dP.y;
        float sqn = dP.x + dP.y;      // = -sq
        float2 dW = sub2(WaC, WbC);
        float wsum = dW.x + dW.y;

        float Thr = kThz * sa;

        // qq (packed squares)
        float2 Qa  = make_float2(q1, q3);
        float2 Qb  = make_float2(q2, q0);
        float2 Qas = make_float2(q3, q1);
        float2 Qbs = make_float2(q0, q2);
        float2 Z1 = mul2(Qbs, Qbs);
        float2 Z2 = mul2(Qa,  Qa);
        float2 Zd = sub2(Z1, Z2);
        float qq = Zd.x - Zd.y;

        // z velocity
        float zd2 = zd * zd;
        float sz  = (zd > 0.f) ? 1.f : ((zd < 0.f) ? -1.f : 0.f);
        float drag = Cdz * (sz * zd2);
        float nzd = zd + ((Thr * qq - drag) - GT);

        // quaternion update via sign-mixed packed halves
        float2 pvd = make_float2(pv, pv);
        float2 qvd = make_float2(qv, qv);
        float2 rvd = make_float2(rv, rv);
        float2 hpmn = mul2(HTmp, pvd);   // (-hp,  hp)
        float2 hpm  = mul2(HTpm, pvd);   // ( hp, -hp)
        float2 hqmn = mul2(HTmp, qvd);   // (-hq,  hq)
        float2 hrn2 = mul2(HTn2, rvd);   // (-hr, -hr)
        float2 hr2  = mul2(HTp2, rvd);   // ( hr,  hr)

        float2 tA = fma2(hrn2, Qas, fma2(hqmn, Qb, mul2(hpmn, Qa)));
        float2 tB = fma2(hr2,  Qb,  fma2(hqmn, Qas, mul2(hpm, Qbs)));
        float2 nq02 = add2(Qbs, tA);  // (q0 - t0, q2 + t2)
        float2 nq13 = add2(Qa,  tB);  // (q1 + t1, q3 + t3)

        // body rates
        float2 qp  = make_float2(qv, pv);
        float2 X1  = mul2(qp, rvd);
        float2 wsd = make_float2(wsum, wsum);
        float2 X2  = mul2(wsd, qp);
        float2 X3  = make_float2(smm, spp);
        float2 r12 = fma2(K, X3, fma2(U, X2, mul2(E, X1)));
        float npv = pv + r12.x;
        float nqv = qv + r12.y;
        float pvqv = pv * qv;
        float r3 = fmaf(nkToz, sqn, e3 * pvqv);
        float nrv = rv + r3;

        float nxz_raw = fmaf(tau, nzd, xz);

        float2 nWa = fma2(TAUD, Da, WaC);
        float2 nWb = fma2(TAUD, Db, WbC);
        float2 nDa = fma2(TAUD, wddA, Da);
        float2 nDb = fma2(TAUD, wddB, Db);

        float diff = nxz_raw - xz;
        float nxz = (fabsf(diff) <= 400.0f) ? nxz_raw : xz;

        float dz = nxz - lbl;
        accf = fmaf(dz, dz, accf);

        xz = nxz; zd = nzd;
        q0 = nq02.x; q2 = nq02.y; q1 = nq13.x; q3 = nq13.y;
        pv = npv; qv = nqv; rv = nrv;
        Wa = nWa; Wb = nWb; Da = nDa; Db = nDb;
    };

    #define LOADS(ii, slot) { \
        const size_t o = (size_t)(ii) * B_DIM; \
        buf[slot][0] = P0[o]; buf[slot][1] = P1[o]; buf[slot][2] = P2[o]; \
        buf[slot][3] = P3[o]; buf[slot][4] = P4[o]; }
    #define STEP(slot) step(buf[slot][0], buf[slot][1], buf[slot][2], \
                            buf[slot][3], buf[slot][4]);

    for (int i = 0; i < 4092; i += 6) {
        STEP(0) LOADS(i + 6,  0)
        STEP(1) LOADS(i + 7,  1)
        STEP(2) LOADS(i + 8,  2)
        STEP(3) LOADS(i + 9,  3)
        STEP(4) LOADS(i + 10, 4)
        STEP(5) LOADS(i + 11, 5)
        acc += (double)accf;
        accf = 0.f;
    }
    STEP(0)
    STEP(1)
    STEP(2)
    acc += (double)accf;

    #undef LOADS
    #undef STEP

    g_loss[b] = acc;
}

// ---------------------------------------------------------------------------
// Kernel 4: deterministic loss reduction -> mean
// ---------------------------------------------------------------------------
__global__ void loss_kernel(float* __restrict__ out)
{
    __shared__ double red[B_DIM];
    red[threadIdx.x] = g_loss[threadIdx.x];
    __syncthreads();
    #pragma unroll
    for (int s = 256; s > 0; s >>= 1) {
        if (threadIdx.x < s) red[threadIdx.x] += red[threadIdx.x + s];
        __syncthreads();
    }
    if (threadIdx.x == 0) out[0] = (float)(red[0] / (double)NELEM);
}

// ---------------------------------------------------------------------------
// Launch
// ---------------------------------------------------------------------------
extern "C" void kernel_launch(void* const* d_in, const int* in_sizes, int n_in,
                              void* d_out, int out_size)
{
    const float* labels = (const float*)d_in[0];
    const float* logits = (const float*)d_in[1];
    const float* u1     = (const float*)d_in[2];
    const float* u2     = (const float*)d_in[3];
    const float* u3     = (const float*)d_in[4];
    const float* u4     = (const float*)d_in[5];
    const float* maxM   = (const float*)d_in[6];
    const float* minM   = (const float*)d_in[7];

    prep_kernel<<<PREP_BLOCKS, 256>>>(logits, u1, u2, u3, u4, maxM, minM, labels);
    hover_kernel<<<1, 256>>>();
    sim_kernel<<<16, 32>>>(labels);
    loss_kernel<<<1, B_DIM>>>((float*)d_out);
}

// round 6
// speedup vs baseline: 1.5158x; 1.5158x over previous
#include <cuda_runtime.h>
#include <math.h>
#include <stdint.h>

// Problem dims
#define T_DIM 4096
#define B_DIM 512
#define NSTEP 4095                  // scan steps (t = 1..4095)
#define NELEM (T_DIM * B_DIM)       // 2,097,152
#define PREP_BLOCKS (NELEM / 256)   // 8192
#define WIN 8
#define NWIN 512                    // ceil(4095/8); window 511 has 7 real steps
#define PROWS 4104                  // padded rows: prefetch of window 512 stays in-bounds
#define PL ((size_t)PROWS * B_DIM)

// ---------------------------------------------------------------------------
// Stage-specific coefficient planes, [step][b] float4 (coalesced).
//   pM0 = (C1, C2, C3, C4)
//   pM1 = (A,  mn, mx, kThz)        A=(-2*damp)*tau2, kThz=kTh*tau/mB
//   pR0 = (e1, e2, -u1, u2)
//   pR1 = (kThd1, kThd2, e3, -kToz)
//   pQ  = (Cd', label, valid, 0)    Cd'=Cd*tau/mB; valid=1 for real steps
// Rows >= 4095 are never written -> stay zero (benign dummy step, valid=0).
// ---------------------------------------------------------------------------
__device__ float4 g_pM0[PL], g_pM1[PL], g_pR0[PL], g_pR1[PL], g_pQ[PL];
__device__ double g_part[PREP_BLOCKS];
__device__ float  g_hover;
__device__ double g_loss[B_DIM];

__device__ __forceinline__ float sc(float g, float base) {
    float t = (0.5f - g) * 95.0f;
    t = t / 100.0f;
    return (1.0f + t) * base;
}

// ---------------------------------------------------------------------------
// Kernel 1: precompute folded coefficients + partial sums of kTh (for hover)
// ---------------------------------------------------------------------------
__global__ void __launch_bounds__(256) prep_kernel(
    const float* __restrict__ logits,
    const float* __restrict__ u1p, const float* __restrict__ u2p,
    const float* __restrict__ u3p, const float* __restrict__ u4p,
    const float* __restrict__ maxp, const float* __restrict__ minp,
    const float* __restrict__ lab)
{
    const int idx = blockIdx.x * 256 + threadIdx.x;
    const float4* lg = reinterpret_cast<const float4*>(logits) + (size_t)idx * 3;
    float4 l0 = lg[0];
    float4 l1 = lg[1];
    float4 l2 = lg[2];

    float kTh = sc(l1.w, 1.076e-05f);

    __shared__ double red[256];
    red[threadIdx.x] = (double)kTh;
    __syncthreads();
    #pragma unroll
    for (int s = 128; s > 0; s >>= 1) {
        if (threadIdx.x < s) red[threadIdx.x] += red[threadIdx.x + s];
        __syncthreads();
    }
    if (threadIdx.x == 0) g_part[blockIdx.x] = red[0];

    const int t = idx >> 9;
    const int b = idx & 511;
    if (t >= 1) {
        const float tau = 0.005f;
        const float TM  = (float)(0.005 / 1.2);   // tau / mB
        const float UPT = (float)(1e-4 * 0.005);  // uP*IRzz*tau

        float dxm  = sc(l0.x, 0.16f);
        float dym  = sc(l0.y, 0.16f);
        float IBxx = sc(l0.w, 0.0123f);
        float IByy = sc(l1.x, 0.0123f);
        float IBzz = sc(l1.y, 0.0123f);
        float Cd   = sc(l1.z, 0.1f);
        float kTo  = sc(l2.x, 1.632e-07f);
        float tau2 = sc(l2.y, 0.015f);
        float kp   = sc(l2.z, 1.0f);
        float damp = sc(l2.w, 1.0f);

        float A   = (-2.0f * damp) * tau2;
        float t2s = tau2 * tau2;
        float C1 = (kp * u1p[idx]) / t2s;
        float C2 = (kp * u2p[idx]) / t2s;
        float C3 = (kp * u3p[idx]) / t2s;
        float C4 = (kp * u4p[idx]) / t2s;

        float Cdz   = Cd * TM;
        float kThz  = kTh * TM;
        float kThd1 = ((kTh * dym) * tau) / IBxx;
        float kThd2 = ((kTh * dxm) * tau) / IByy;
        float e1 = ((IByy - IBzz) * tau) / IBxx;
        float u1 = UPT / IBxx;
        float e2 = ((IBzz - IBxx) * tau) / IByy;
        float u2 = UPT / IByy;
        float e3 = ((IBxx - IByy) * tau) / IBzz;
        float kToz = (kTo * tau) / IBzz;

        size_t o = (size_t)(t - 1) * B_DIM + b;
        g_pM0[o] = make_float4(C1, C2, C3, C4);
        g_pM1[o] = make_float4(A, minp[idx], maxp[idx], kThz);
        g_pR0[o] = make_float4(e1, e2, -u1, u2);
        g_pR1[o] = make_float4(kThd1, kThd2, e3, -kToz);
        g_pQ[o]  = make_float4(Cdz, lab[idx], 1.0f, 0.f);
    }
}

// ---------------------------------------------------------------------------
// Kernel 2: hover = sqrt(max(mB*g/(4*mean(kTh)+eps), 1e-6))
// ---------------------------------------------------------------------------
__global__ void hover_kernel()
{
    __shared__ double red[256];
    double s = 0.0;
    for (int i = threadIdx.x; i < PREP_BLOCKS; i += 256) s += g_part[i];
    red[threadIdx.x] = s;
    __syncthreads();
    #pragma unroll
    for (int st = 128; st > 0; st >>= 1) {
        if (threadIdx.x < st) red[threadIdx.x] += red[threadIdx.x + st];
        __syncthreads();
    }
    if (threadIdx.x == 0) {
        float m   = (float)(red[0] / (double)NELEM);
        float den = 4.0f * m + 1e-12f;
        float v   = (float)(1.2 * 9.81) / den;
        v = fmaxf(v, 1e-6f);
        g_hover = sqrtf(v);
    }
}

// ---------------------------------------------------------------------------
// Kernel 3: 3-warp pipelined simulation. 16 blocks x 96 threads.
// Warp 0 = Motors, Warp 1 = Rates, Warp 2 = Quaternion/z/loss.
// Stages skewed by one 8-step window, double-buffered SMEM rings,
// one __syncthreads per window. Per-stage 8-step register prefetch ring.
// ---------------------------------------------------------------------------
__global__ void __launch_bounds__(96, 1) sim_kernel(const float* __restrict__ labels)
{
    const int wid  = threadIdx.x >> 5;
    const int lane = threadIdx.x & 31;
    const int b    = blockIdx.x * 32 + lane;

    const float tau = 0.005f;
    const float HT  = 0.0025f;   // tau * 0.5
    const float GT  = 0.04905f;  // g * tau

    __shared__ float4 sMR[2][WIN][32];  // (spp, smm, sqn, wsum)
    __shared__ float  sMQ[2][WIN][32];  // Thr = kThz * sa
    __shared__ float4 sRQ[2][WIN][32];  // (hp, hq, hr, 0)

    // ---------------- stage M state ----------------
    const float hover = g_hover;
    float w1 = hover, w2 = hover, w3 = hover, w4 = hover;
    float wd1 = 0.f, wd2 = 0.f, wd3 = 0.f, wd4 = 0.f;
    const float4* __restrict__ PM0 = g_pM0 + b;
    const float4* __restrict__ PM1 = g_pM1 + b;
    float4 bm0[WIN], bm1[WIN];

    // ---------------- stage R state ----------------
    float pv = 0.f, qv = 0.f, rv = 0.f;
    const float4* __restrict__ PR0 = g_pR0 + b;
    const float4* __restrict__ PR1 = g_pR1 + b;
    float4 br0[WIN], br1[WIN];

    // ---------------- stage Q state ----------------
    float xz = 0.f, zd = 0.f;
    float q0 = 1.f, q1 = 0.f, q2 = 0.f, q3 = 0.f;
    double acc = 0.0;
    const float4* __restrict__ PQ = g_pQ + b;
    float4 bq[WIN];

    // preload window 0 for the relevant stage
    if (wid == 0) {
        #pragma unroll
        for (int j = 0; j < WIN; ++j) {
            bm0[j] = PM0[(size_t)j * B_DIM];
            bm1[j] = PM1[(size_t)j * B_DIM];
        }
    } else if (wid == 1) {
        #pragma unroll
        for (int j = 0; j < WIN; ++j) {
            br0[j] = PR0[(size_t)j * B_DIM];
            br1[j] = PR1[(size_t)j * B_DIM];
        }
    } else {
        #pragma unroll
        for (int j = 0; j < WIN; ++j) {
            bq[j] = PQ[(size_t)j * B_DIM];
        }
        float l0 = labels[b];
        acc = (double)l0 * (double)l0;   // (pred_z[0]=0 - actual_z[0])^2
    }

    for (int p = 0; p < NWIN + 2; ++p) {
        if (wid == 0) {
            // -------- Motors: window p --------
            if (p < NWIN) {
                const int s0  = p * WIN;
                const int par = p & 1;
                #pragma unroll
                for (int j = 0; j < WIN; ++j) {
                    const float4 c0 = bm0[j];   // C1..C4
                    const float4 c1 = bm1[j];   // A, mn, mx, kThz
                    float wdd1 = fmaf(c1.x, wd1, -w1) + c0.x;
                    float wdd2 = fmaf(c1.x, wd2, -w2) + c0.y;
                    float wdd3 = fmaf(c1.x, wd3, -w3) + c0.z;
                    float wdd4 = fmaf(c1.x, wd4, -w4) + c0.w;

                    float w1c = fminf(fmaxf(w1, c1.y), c1.z);
                    float w2c = fminf(fmaxf(w2, c1.y), c1.z);
                    float w3c = fminf(fmaxf(w3, c1.y), c1.z);
                    float w4c = fminf(fmaxf(w4, c1.y), c1.z);

                    float s1 = w1c * w1c, s2 = w2c * w2c;
                    float s3 = w3c * w3c, s4 = w4c * w4c;
                    float a12 = s1 + s2, a34 = s3 + s4;
                    float d12 = s1 - s2, d34 = s3 - s4;
                    float sa  = a12 + a34;
                    float spp = a12 - a34;
                    float smm = d12 - d34;
                    float sqn = d12 + d34;           // = s1-s2+s3-s4
                    float wsum = (w1c - w2c) + (w3c - w4c);
                    float Thr = c1.w * sa;           // kThz * sa

                    sMR[par][j][lane] = make_float4(spp, smm, sqn, wsum);
                    sMQ[par][j][lane] = Thr;

                    w1 = fmaf(tau, wd1, w1c);
                    w2 = fmaf(tau, wd2, w2c);
                    w3 = fmaf(tau, wd3, w3c);
                    w4 = fmaf(tau, wd4, w4c);
                    wd1 = fmaf(tau, wdd1, wd1);
                    wd2 = fmaf(tau, wdd2, wd2);
                    wd3 = fmaf(tau, wdd3, wd3);
                    wd4 = fmaf(tau, wdd4, wd4);

                    bm0[j] = PM0[(size_t)(s0 + WIN + j) * B_DIM];
                    bm1[j] = PM1[(size_t)(s0 + WIN + j) * B_DIM];
                }
            }
        } else if (wid == 1) {
            // -------- Rates: window p-1 --------
            if (p >= 1 && p <= NWIN) {
                const int w   = p - 1;
                const int s0  = w * WIN;
                const int par = w & 1;
                float4 m[WIN];
                #pragma unroll
                for (int j = 0; j < WIN; ++j) m[j] = sMR[par][j][lane];
                #pragma unroll
                for (int j = 0; j < WIN; ++j) {
                    const float4 r0 = br0[j];   // e1, e2, -u1, u2
                    const float4 r1 = br1[j];   // kThd1, kThd2, e3, -kToz
                    const float4 mm = m[j];     // spp, smm, sqn, wsum

                    float qvrv = qv * rv, pvrv = pv * rv, pvqv = pv * qv;
                    float wq = mm.w * qv, wp = mm.w * pv;

                    float t1 = r0.x * qvrv;
                    t1 = fmaf(r0.z, wq, t1);
                    t1 = fmaf(r1.x, mm.y, t1);
                    float npv = pv + t1;

                    float t2 = r0.y * pvrv;
                    t2 = fmaf(r0.w, wp, t2);
                    t2 = fmaf(r1.y, mm.x, t2);
                    float nqv = qv + t2;

                    float t3 = r1.z * pvqv;
                    t3 = fmaf(r1.w, mm.z, t3);
                    float nrv = rv + t3;

                    // half-rates from CURRENT (pre-update) state, as reference
                    float hp = HT * pv, hq = HT * qv, hr = HT * rv;
                    sRQ[par][j][lane] = make_float4(hp, hq, hr, 0.f);

                    pv = npv; qv = nqv; rv = nrv;

                    br0[j] = PR0[(size_t)(s0 + WIN + j) * B_DIM];
                    br1[j] = PR1[(size_t)(s0 + WIN + j) * B_DIM];
                }
            }
        } else {
            // -------- Quaternion / z / loss: window p-2 --------
            if (p >= 2) {
                const int w   = p - 2;
                const int s0  = w * WIN;
                const int par = w & 1;
                float4 h[WIN];
                float  thr[WIN];
                #pragma unroll
                for (int j = 0; j < WIN; ++j) {
                    h[j]   = sRQ[par][j][lane];
                    thr[j] = sMQ[par][j][lane];
                }
                float accf = 0.f;
                #pragma unroll
                for (int j = 0; j < WIN; ++j) {
                    const float4 qc = bq[j];  // Cd', label, valid, 0
                    const float hp = h[j].x, hq = h[j].y, hr = h[j].z;
                    const float Thr = thr[j];

                    float sq0 = q0 * q0, sq1 = q1 * q1;
                    float sq2 = q2 * q2, sq3 = q3 * q3;
                    float qq = (sq0 - sq1) - (sq2 - sq3);

                    float zd2 = zd * zd;
                    float sz = (zd > 0.f) ? 1.f : ((zd < 0.f) ? -1.f : 0.f);
                    float drag = qc.x * (sz * zd2);
                    float nzd = zd + ((Thr * qq - drag) - GT);

                    float tA0 = fmaf(-hr, q3, fmaf(-hq, q2, (-hp) * q1));
                    float tA2 = fmaf(-hr, q1, fmaf( hq, q0,   hp  * q3));
                    float tB1 = fmaf( hr, q2, fmaf(-hq, q3,   hp  * q0));
                    float tB3 = fmaf( hr, q0, fmaf( hq, q1, (-hp) * q2));
                    float nq0 = q0 + tA0;
                    float nq2 = q2 + tA2;
                    float nq1 = q1 + tB1;
                    float nq3 = q3 + tB3;

                    float nxz_raw = fmaf(tau, nzd, xz);
                    float diff = nxz_raw - xz;
                    float nxz = (fabsf(diff) <= 400.0f) ? nxz_raw : xz;

                    float dzv = (nxz - qc.y) * qc.z;   // valid-weighted
                    accf = fmaf(dzv, dzv, accf);

                    xz = nxz; zd = nzd;
                    q0 = nq0; q1 = nq1; q2 = nq2; q3 = nq3;

                    bq[j] = PQ[(size_t)(s0 + WIN + j) * B_DIM];
                }
                acc += (double)accf;
            }
        }
        __syncthreads();
    }

    if (wid == 2) g_loss[b] = acc;
}

// ---------------------------------------------------------------------------
// Kernel 4: deterministic loss reduction -> mean
// ---------------------------------------------------------------------------
__global__ void loss_kernel(float* __restrict__ out)
{
    __shared__ double red[B_DIM];
    red[threadIdx.x] = g_loss[threadIdx.x];
    __syncthreads();
    #pragma unroll
    for (int s = 256; s > 0; s >>= 1) {
        if (threadIdx.x < s) red[threadIdx.x] += red[threadIdx.x + s];
        __syncthreads();
    }
    if (threadIdx.x == 0) out[0] = (float)(red[0] / (double)NELEM);
}

// ---------------------------------------------------------------------------
// Launch
// ---------------------------------------------------------------------------
extern "C" void kernel_launch(void* const* d_in, const int* in_sizes, int n_in,
                              void* d_out, int out_size)
{
    const float* labels = (const float*)d_in[0];
    const float* logits = (const float*)d_in[1];
    const float* u1     = (const float*)d_in[2];
    const float* u2     = (const float*)d_in[3];
    const float* u3     = (const float*)d_in[4];
    const float* u4     = (const float*)d_in[5];
    const float* maxM   = (const float*)d_in[6];
    const float* minM   = (const float*)d_in[7];

    prep_kernel<<<PREP_BLOCKS, 256>>>(logits, u1, u2, u3, u4, maxM, minM, labels);
    hover_kernel<<<1, 256>>>();
    sim_kernel<<<16, 96>>>(labels);
    loss_kernel<<<1, B_DIM>>>((float*)d_out);
}

// round 7
// speedup vs baseline: 1.5274x; 1.0076x over previous
#include <cuda_runtime.h>
#include <math.h>
#include <stdint.h>

// Problem dims
#define T_DIM 4096
#define B_DIM 512
#define NSTEP 4095                  // scan steps (t = 1..4095)
#define NELEM (T_DIM * B_DIM)       // 2,097,152
#define PREP_BLOCKS (NELEM / 256)   // 8192
#define WIN 8
#define NWIN 512                    // window 511 has 7 real steps + 1 dummy
#define PROWS 4104                  // padded rows: prefetch stays in-bounds
#define PL ((size_t)PROWS * B_DIM)

// ---------------------------------------------------------------------------
// Stage-specific coefficient planes, [step][b] (coalesced). Rows >= 4095
// stay zero (benign dummy step).
//   pM0 = (C1, C2, C3, C4)
//   pM1 = (A,  mn, mx, 0)           A=(-2*damp)*tau2
//   kThz plane (float)              kTh*tau/mB
//   pR0 = (e1, e2, -u1, u2)
//   pR1 = (kThd1, kThd2, e3, -kToz)
//   pQ  = (Cd', label)              Cd'=Cd*tau/mB
// ---------------------------------------------------------------------------
__device__ float4 g_pM0[PL], g_pM1[PL], g_pR0[PL], g_pR1[PL];
__device__ float  g_kThz[PL];
__device__ float2 g_pQ[PL];
__device__ float  g_part[PREP_BLOCKS];
__device__ float  g_hover;
__device__ double g_loss[B_DIM];

__device__ __forceinline__ float sc(float g, float base) {
    float t = (0.5f - g) * 95.0f;
    t = t / 100.0f;
    return (1.0f + t) * base;
}

// ---------------------------------------------------------------------------
// Kernel 1: precompute folded coefficients + partial sums of kTh (for hover)
// ---------------------------------------------------------------------------
__global__ void __launch_bounds__(256) prep_kernel(
    const float* __restrict__ logits,
    const float* __restrict__ u1p, const float* __restrict__ u2p,
    const float* __restrict__ u3p, const float* __restrict__ u4p,
    const float* __restrict__ maxp, const float* __restrict__ minp,
    const float* __restrict__ lab)
{
    const int idx = blockIdx.x * 256 + threadIdx.x;
    const float4* lg = reinterpret_cast<const float4*>(logits) + (size_t)idx * 3;
    float4 l0 = lg[0];
    float4 l1 = lg[1];
    float4 l2 = lg[2];

    float kTh = sc(l1.w, 1.076e-05f);

    // deterministic float block reduction of kTh
    __shared__ float red[256];
    red[threadIdx.x] = kTh;
    __syncthreads();
    #pragma unroll
    for (int s = 128; s > 0; s >>= 1) {
        if (threadIdx.x < s) red[threadIdx.x] += red[threadIdx.x + s];
        __syncthreads();
    }
    if (threadIdx.x == 0) g_part[blockIdx.x] = red[0];

    const int t = idx >> 9;
    const int b = idx & 511;
    if (t >= 1) {
        const float tau = 0.005f;
        const float TM  = (float)(0.005 / 1.2);   // tau / mB
        const float UPT = (float)(1e-4 * 0.005);  // uP*IRzz*tau

        float dxm  = sc(l0.x, 0.16f);
        float dym  = sc(l0.y, 0.16f);
        float IBxx = sc(l0.w, 0.0123f);
        float IByy = sc(l1.x, 0.0123f);
        float IBzz = sc(l1.y, 0.0123f);
        float Cd   = sc(l1.z, 0.1f);
        float kTo  = sc(l2.x, 1.632e-07f);
        float tau2 = sc(l2.y, 0.015f);
        float kp   = sc(l2.z, 1.0f);
        float damp = sc(l2.w, 1.0f);

        float A    = (-2.0f * damp) * tau2;
        float rt2s = __fdividef(1.0f, tau2 * tau2);
        float C1 = (kp * u1p[idx]) * rt2s;
        float C2 = (kp * u2p[idx]) * rt2s;
        float C3 = (kp * u3p[idx]) * rt2s;
        float C4 = (kp * u4p[idx]) * rt2s;

        float rx = __fdividef(1.0f, IBxx);
        float ry = __fdividef(1.0f, IByy);
        float rz = __fdividef(1.0f, IBzz);

        float Cdz   = Cd * TM;
        float kThz  = kTh * TM;
        float kThd1 = ((kTh * dym) * tau) * rx;
        float kThd2 = ((kTh * dxm) * tau) * ry;
        float e1 = ((IByy - IBzz) * tau) * rx;
        float u1 = UPT * rx;
        float e2 = ((IBzz - IBxx) * tau) * ry;
        float u2 = UPT * ry;
        float e3 = ((IBxx - IByy) * tau) * rz;
        float kToz = (kTo * tau) * rz;

        size_t o = (size_t)(t - 1) * B_DIM + b;
        g_pM0[o]  = make_float4(C1, C2, C3, C4);
        g_pM1[o]  = make_float4(A, minp[idx], maxp[idx], 0.f);
        g_kThz[o] = kThz;
        g_pR0[o]  = make_float4(e1, e2, -u1, u2);
        g_pR1[o]  = make_float4(kThd1, kThd2, e3, -kToz);
        g_pQ[o]   = make_float2(Cdz, lab[idx]);
    }
}

// ---------------------------------------------------------------------------
// Kernel 2: hover = sqrt(max(mB*g/(4*mean(kTh)+eps), 1e-6))
// ---------------------------------------------------------------------------
__global__ void hover_kernel()
{
    __shared__ double red[256];
    double s = 0.0;
    for (int i = threadIdx.x; i < PREP_BLOCKS; i += 256) s += (double)g_part[i];
    red[threadIdx.x] = s;
    __syncthreads();
    #pragma unroll
    for (int st = 128; st > 0; st >>= 1) {
        if (threadIdx.x < st) red[threadIdx.x] += red[threadIdx.x + st];
        __syncthreads();
    }
    if (threadIdx.x == 0) {
        float m   = (float)(red[0] / (double)NELEM);
        float den = 4.0f * m + 1e-12f;
        float v   = (float)(1.2 * 9.81) / den;
        v = fmaxf(v, 1e-6f);
        g_hover = sqrtf(v);
    }
}

// ---------------------------------------------------------------------------
// Kernel 3: 5-warp pipelined simulation. 16 blocks x 160 threads.
// W0 Motors | W1 Sums/Thr | W2 Rates | W3 Quaternion | W4 z/loss
// Stages skewed by one 8-step window each; SMEM rings (depth 2, Thr depth 4);
// one __syncthreads per window; per-stage register prefetch 1 window ahead.
// ---------------------------------------------------------------------------
__global__ void __launch_bounds__(160, 1) sim_kernel(const float* __restrict__ labels)
{
    const int wid  = threadIdx.x >> 5;
    const int lane = threadIdx.x & 31;
    const int b    = blockIdx.x * 32 + lane;

    const float tau = 0.005f;
    const float HT  = 0.0025f;   // tau * 0.5
    const float GT  = 0.04905f;  // g * tau

    __shared__ float4 sW[2][WIN][32];   // w1c..w4c        W0 -> W1
    __shared__ float4 sS[2][WIN][32];   // spp,smm,sqn,wsum W1 -> W2
    __shared__ float  sT[4][WIN][32];   // Thr             W1 -> W4 (3-window hop)
    __shared__ float4 sH[2][WIN][32];   // hp,hq,hr,0      W2 -> W3
    __shared__ float4 sQ[2][WIN][32];   // pre-update q    W3 -> W4

    // ---- W0 state ----
    const float hover = g_hover;
    float w1 = hover, w2 = hover, w3 = hover, w4 = hover;
    float wd1 = 0.f, wd2 = 0.f, wd3 = 0.f, wd4 = 0.f;
    const float4* __restrict__ PM0 = g_pM0 + b;
    const float4* __restrict__ PM1 = g_pM1 + b;
    float4 bm0[WIN], bm1[WIN];

    // ---- W1 state ----
    const float* __restrict__ PKT = g_kThz + b;
    float bk[WIN];

    // ---- W2 state ----
    float pv = 0.f, qv = 0.f, rv = 0.f;
    const float4* __restrict__ PR0 = g_pR0 + b;
    const float4* __restrict__ PR1 = g_pR1 + b;
    float4 br0[WIN], br1[WIN];

    // ---- W3 state ----
    float q0 = 1.f, q1 = 0.f, q2 = 0.f, q3 = 0.f;

    // ---- W4 state ----
    float xz = 0.f, zd = 0.f;
    double acc = 0.0;
    const float2* __restrict__ PQ = g_pQ + b;
    float2 bq[WIN];

    // preload window 0 of the relevant planes
    if (wid == 0) {
        #pragma unroll
        for (int j = 0; j < WIN; ++j) {
            bm0[j] = PM0[(size_t)j * B_DIM];
            bm1[j] = PM1[(size_t)j * B_DIM];
        }
    } else if (wid == 1) {
        #pragma unroll
        for (int j = 0; j < WIN; ++j) bk[j] = PKT[(size_t)j * B_DIM];
    } else if (wid == 2) {
        #pragma unroll
        for (int j = 0; j < WIN; ++j) {
            br0[j] = PR0[(size_t)j * B_DIM];
            br1[j] = PR1[(size_t)j * B_DIM];
        }
    } else if (wid == 4) {
        #pragma unroll
        for (int j = 0; j < WIN; ++j) bq[j] = PQ[(size_t)j * B_DIM];
        float l0 = labels[b];
        acc = (double)l0 * (double)l0;   // (pred_z[0]=0 - actual_z[0])^2
    }

    for (int p = 0; p < NWIN + 4; ++p) {
        if (wid == 0) {
            // -------- Motors: window p --------
            if (p < NWIN) {
                const int s0  = p * WIN;
                const int par = p & 1;
                #pragma unroll
                for (int j = 0; j < WIN; ++j) {
                    const float4 c0 = bm0[j];   // C1..C4
                    const float4 c1 = bm1[j];   // A, mn, mx
                    float wdd1 = fmaf(c1.x, wd1, -w1) + c0.x;
                    float wdd2 = fmaf(c1.x, wd2, -w2) + c0.y;
                    float wdd3 = fmaf(c1.x, wd3, -w3) + c0.z;
                    float wdd4 = fmaf(c1.x, wd4, -w4) + c0.w;

                    float w1c = fminf(fmaxf(w1, c1.y), c1.z);
                    float w2c = fminf(fmaxf(w2, c1.y), c1.z);
                    float w3c = fminf(fmaxf(w3, c1.y), c1.z);
                    float w4c = fminf(fmaxf(w4, c1.y), c1.z);

                    sW[par][j][lane] = make_float4(w1c, w2c, w3c, w4c);

                    w1 = fmaf(tau, wd1, w1c);
                    w2 = fmaf(tau, wd2, w2c);
                    w3 = fmaf(tau, wd3, w3c);
                    w4 = fmaf(tau, wd4, w4c);
                    wd1 = fmaf(tau, wdd1, wd1);
                    wd2 = fmaf(tau, wdd2, wd2);
                    wd3 = fmaf(tau, wdd3, wd3);
                    wd4 = fmaf(tau, wdd4, wd4);

                    bm0[j] = PM0[(size_t)(s0 + WIN + j) * B_DIM];
                    bm1[j] = PM1[(size_t)(s0 + WIN + j) * B_DIM];
                }
            }
        } else if (wid == 1) {
            // -------- Sums/Thr: window p-1 --------
            if (p >= 1 && p <= NWIN) {
                const int w    = p - 1;
                const int s0   = w * WIN;
                const int par  = w & 1;
                const int par4 = w & 3;
                float4 wv[WIN];
                #pragma unroll
                for (int j = 0; j < WIN; ++j) wv[j] = sW[par][j][lane];
                #pragma unroll
                for (int j = 0; j < WIN; ++j) {
                    const float4 wc = wv[j];
                    float s1 = wc.x * wc.x, s2 = wc.y * wc.y;
                    float s3 = wc.z * wc.z, s4 = wc.w * wc.w;
                    float a12 = s1 + s2, a34 = s3 + s4;
                    float d12 = s1 - s2, d34 = s3 - s4;
                    float sa  = a12 + a34;
                    float spp = a12 - a34;
                    float smm = d12 - d34;
                    float sqn = d12 + d34;
                    float wsum = (wc.x - wc.y) + (wc.z - wc.w);
                    float Thr = bk[j] * sa;

                    sS[par][j][lane]  = make_float4(spp, smm, sqn, wsum);
                    sT[par4][j][lane] = Thr;

                    bk[j] = PKT[(size_t)(s0 + WIN + j) * B_DIM];
                }
            }
        } else if (wid == 2) {
            // -------- Rates: window p-2 --------
            if (p >= 2 && p <= NWIN + 1) {
                const int w   = p - 2;
                const int s0  = w * WIN;
                const int par = w & 1;
                float4 m[WIN];
                #pragma unroll
                for (int j = 0; j < WIN; ++j) m[j] = sS[par][j][lane];
                #pragma unroll
                for (int j = 0; j < WIN; ++j) {
                    const float4 r0 = br0[j];   // e1, e2, -u1, u2
                    const float4 r1 = br1[j];   // kThd1, kThd2, e3, -kToz
                    const float4 mm = m[j];     // spp, smm, sqn, wsum

                    float qvrv = qv * rv, pvrv = pv * rv, pvqv = pv * qv;
                    float wq = mm.w * qv, wp = mm.w * pv;

                    float t1 = r0.x * qvrv;
                    t1 = fmaf(r0.z, wq, t1);
                    t1 = fmaf(r1.x, mm.y, t1);
                    float npv = pv + t1;

                    float t2 = r0.y * pvrv;
                    t2 = fmaf(r0.w, wp, t2);
                    t2 = fmaf(r1.y, mm.x, t2);
                    float nqv = qv + t2;

                    float t3 = r1.z * pvqv;
                    t3 = fmaf(r1.w, mm.z, t3);
                    float nrv = rv + t3;

                    // half-rates from CURRENT (pre-update) state
                    float hp = HT * pv, hq = HT * qv, hr = HT * rv;
                    sH[par][j][lane] = make_float4(hp, hq, hr, 0.f);

                    pv = npv; qv = nqv; rv = nrv;

                    br0[j] = PR0[(size_t)(s0 + WIN + j) * B_DIM];
                    br1[j] = PR1[(size_t)(s0 + WIN + j) * B_DIM];
                }
            }
        } else if (wid == 3) {
            // -------- Quaternion: window p-3 --------
            if (p >= 3 && p <= NWIN + 2) {
                const int w   = p - 3;
                const int par = w & 1;
                float4 h[WIN];
                #pragma unroll
                for (int j = 0; j < WIN; ++j) h[j] = sH[par][j][lane];
                #pragma unroll
                for (int j = 0; j < WIN; ++j) {
                    const float hp = h[j].x, hq = h[j].y, hr = h[j].z;

                    // pre-update q goes to W4 (z-dynamics uses carry q)
                    sQ[par][j][lane] = make_float4(q0, q1, q2, q3);

                    float tA0 = fmaf(-hr, q3, fmaf(-hq, q2, (-hp) * q1));
                    float tA2 = fmaf(-hr, q1, fmaf( hq, q0,   hp  * q3));
                    float tB1 = fmaf( hr, q2, fmaf(-hq, q3,   hp  * q0));
                    float tB3 = fmaf( hr, q0, fmaf( hq, q1, (-hp) * q2));
                    float nq0 = q0 + tA0;
                    float nq2 = q2 + tA2;
                    float nq1 = q1 + tB1;
                    float nq3 = q3 + tB3;
                    q0 = nq0; q1 = nq1; q2 = nq2; q3 = nq3;
                }
            }
        } else {
            // -------- z / loss: window p-4 --------
            if (p >= 4) {
                const int w    = p - 4;
                const int s0   = w * WIN;
                const int par  = w & 1;
                const int par4 = w & 3;
                float4 qv4[WIN];
                float  thr[WIN];
                #pragma unroll
                for (int j = 0; j < WIN; ++j) {
                    qv4[j] = sQ[par][j][lane];
                    thr[j] = sT[par4][j][lane];
                }
                float accf = 0.f;
                #pragma unroll
                for (int j = 0; j < WIN; ++j) {
                    const float2 qc = bq[j];        // Cd', label
                    const float4 qd = qv4[j];
                    const float Thr = thr[j];

                    float sq0 = qd.x * qd.x, sq1 = qd.y * qd.y;
                    float sq2 = qd.z * qd.z, sq3 = qd.w * qd.w;
                    float qq = (sq0 - sq1) - (sq2 - sq3);

                    float zd2 = zd * zd;
                    float sz = (zd > 0.f) ? 1.f : ((zd < 0.f) ? -1.f : 0.f);
                    float drag = qc.x * (sz * zd2);
                    float nzd = zd + ((Thr * qq - drag) - GT);

                    float nxz_raw = fmaf(tau, nzd, xz);
                    float diff = nxz_raw - xz;
                    float nxz = (fabsf(diff) <= 400.0f) ? nxz_raw : xz;

                    float dz = nxz - qc.y;
                    if (s0 + j < NSTEP) accf = fmaf(dz, dz, accf);

                    xz = nxz; zd = nzd;

                    bq[j] = PQ[(size_t)(s0 + WIN + j) * B_DIM];
                }
                acc += (double)accf;
            }
        }
        __syncthreads();
    }

    if (wid == 4) g_loss[b] = acc;
}

// ---------------------------------------------------------------------------
// Kernel 4: deterministic loss reduction -> mean
// ---------------------------------------------------------------------------
__global__ void loss_kernel(float* __restrict__ out)
{
    __shared__ double red[B_DIM];
    red[threadIdx.x] = g_loss[threadIdx.x];
    __syncthreads();
    #pragma unroll
    for (int s = 256; s > 0; s >>= 1) {
        if (threadIdx.x < s) red[threadIdx.x] += red[threadIdx.x + s];
        __syncthreads();
    }
    if (threadIdx.x == 0) out[0] = (float)(red[0] / (double)NELEM);
}

// ---------------------------------------------------------------------------
// Launch
// ---------------------------------------------------------------------------
extern "C" void kernel_launch(void* const* d_in, const int* in_sizes, int n_in,
                              void* d_out, int out_size)
{
    const float* labels = (const float*)d_in[0];
    const float* logits = (const float*)d_in[1];
    const float* u1     = (const float*)d_in[2];
    const float* u2     = (const float*)d_in[3];
    const float* u3     = (const float*)d_in[4];
    const float* u4     = (const float*)d_in[5];
    const float* maxM   = (const float*)d_in[6];
    const float* minM   = (const float*)d_in[7];

    prep_kernel<<<PREP_BLOCKS, 256>>>(logits, u1, u2, u3, u4, maxM, minM, labels);
    hover_kernel<<<1, 256>>>();
    sim_kernel<<<16, 160>>>(labels);
    loss_kernel<<<1, B_DIM>>>((float*)d_out);
}

// round 8
// speedup vs baseline: 1.6544x; 1.0832x over previous
#include <cuda_runtime.h>
#include <math.h>
#include <stdint.h>

// Problem dims
#define T_DIM 4096
#define B_DIM 512
#define NSTEP 4095                  // scan steps (t = 1..4095)
#define NELEM (T_DIM * B_DIM)       // 2,097,152
#define PREP_BLOCKS (NELEM / 256)   // 8192
#define WIN 8
#define NWIN 512                    // window 511 has 7 real steps + 1 dummy
#define PROWS 4104                  // padded rows: prefetch stays in-bounds
#define PL ((size_t)PROWS * B_DIM)

#define BARRIER() asm volatile("bar.sync 0;" ::: "memory")

// ---------------------------------------------------------------------------
// Stage-specific coefficient planes, [step][b] (coalesced). Rows >= 4095
// stay zero (benign dummy step).
// ---------------------------------------------------------------------------
__device__ float4 g_pM0[PL], g_pM1[PL], g_pR0[PL], g_pR1[PL];
__device__ float  g_kThz[PL];
__device__ float2 g_pQ[PL];
__device__ float  g_part[PREP_BLOCKS];
__device__ float  g_hover;
__device__ double g_loss[B_DIM];

__device__ __forceinline__ float sc(float g, float base) {
    float t = (0.5f - g) * 95.0f;
    t = t / 100.0f;
    return (1.0f + t) * base;
}

// ---------------------------------------------------------------------------
// Kernel 1: precompute folded coefficients + partial sums of kTh (for hover)
// ---------------------------------------------------------------------------
__global__ void __launch_bounds__(256) prep_kernel(
    const float* __restrict__ logits,
    const float* __restrict__ u1p, const float* __restrict__ u2p,
    const float* __restrict__ u3p, const float* __restrict__ u4p,
    const float* __restrict__ maxp, const float* __restrict__ minp,
    const float* __restrict__ lab)
{
    const int idx = blockIdx.x * 256 + threadIdx.x;
    const float4* lg = reinterpret_cast<const float4*>(logits) + (size_t)idx * 3;
    float4 l0 = lg[0];
    float4 l1 = lg[1];
    float4 l2 = lg[2];

    float kTh = sc(l1.w, 1.076e-05f);

    __shared__ float red[256];
    red[threadIdx.x] = kTh;
    __syncthreads();
    #pragma unroll
    for (int s = 128; s > 0; s >>= 1) {
        if (threadIdx.x < s) red[threadIdx.x] += red[threadIdx.x + s];
        __syncthreads();
    }
    if (threadIdx.x == 0) g_part[blockIdx.x] = red[0];

    const int t = idx >> 9;
    const int b = idx & 511;
    if (t >= 1) {
        const float tau = 0.005f;
        const float TM  = (float)(0.005 / 1.2);   // tau / mB
        const float UPT = (float)(1e-4 * 0.005);  // uP*IRzz*tau

        float dxm  = sc(l0.x, 0.16f);
        float dym  = sc(l0.y, 0.16f);
        float IBxx = sc(l0.w, 0.0123f);
        float IByy = sc(l1.x, 0.0123f);
        float IBzz = sc(l1.y, 0.0123f);
        float Cd   = sc(l1.z, 0.1f);
        float kTo  = sc(l2.x, 1.632e-07f);
        float tau2 = sc(l2.y, 0.015f);
        float kp   = sc(l2.z, 1.0f);
        float damp = sc(l2.w, 1.0f);

        float A    = (-2.0f * damp) * tau2;
        float rt2s = __fdividef(1.0f, tau2 * tau2);
        float C1 = (kp * u1p[idx]) * rt2s;
        float C2 = (kp * u2p[idx]) * rt2s;
        float C3 = (kp * u3p[idx]) * rt2s;
        float C4 = (kp * u4p[idx]) * rt2s;

        float rx = __fdividef(1.0f, IBxx);
        float ry = __fdividef(1.0f, IByy);
        float rz = __fdividef(1.0f, IBzz);

        float Cdz   = Cd * TM;
        float kThz  = kTh * TM;
        float kThd1 = ((kTh * dym) * tau) * rx;
        float kThd2 = ((kTh * dxm) * tau) * ry;
        float e1 = ((IByy - IBzz) * tau) * rx;
        float u1 = UPT * rx;
        float e2 = ((IBzz - IBxx) * tau) * ry;
        float u2 = UPT * ry;
        float e3 = ((IBxx - IByy) * tau) * rz;
        float kToz = (kTo * tau) * rz;

        size_t o = (size_t)(t - 1) * B_DIM + b;
        g_pM0[o]  = make_float4(C1, C2, C3, C4);
        g_pM1[o]  = make_float4(A, minp[idx], maxp[idx], 0.f);
        g_kThz[o] = kThz;
        g_pR0[o]  = make_float4(e1, e2, -u1, u2);
        g_pR1[o]  = make_float4(kThd1, kThd2, e3, -kToz);
        g_pQ[o]   = make_float2(Cdz, lab[idx]);
    }
}

// ---------------------------------------------------------------------------
// Kernel 2: hover = sqrt(max(mB*g/(4*mean(kTh)+eps), 1e-6))
// ---------------------------------------------------------------------------
__global__ void hover_kernel()
{
    __shared__ double red[256];
    double s = 0.0;
    for (int i = threadIdx.x; i < PREP_BLOCKS; i += 256) s += (double)g_part[i];
    red[threadIdx.x] = s;
    __syncthreads();
    #pragma unroll
    for (int st = 128; st > 0; st >>= 1) {
        if (threadIdx.x < st) red[threadIdx.x] += red[threadIdx.x + st];
        __syncthreads();
    }
    if (threadIdx.x == 0) {
        float m   = (float)(red[0] / (double)NELEM);
        float den = 4.0f * m + 1e-12f;
        float v   = (float)(1.2 * 9.81) / den;
        v = fmaxf(v, 1e-6f);
        g_hover = sqrtf(v);
    }
}

// ---------------------------------------------------------------------------
// Kernel 3: warp-SPECIALIZED 5-stage pipeline. 16 blocks x 160 threads.
// Each warp owns its branch + loop + buffers (no cross-stage register
// liveness -> no spills). bar.sync 0 executed exactly NWIN+4 times per warp.
// ---------------------------------------------------------------------------
__global__ void __launch_bounds__(160, 1) sim_kernel(const float* __restrict__ labels)
{
    const int wid  = threadIdx.x >> 5;
    const int lane = threadIdx.x & 31;
    const int b    = blockIdx.x * 32 + lane;

    const float tau = 0.005f;
    const float HT  = 0.0025f;   // tau * 0.5
    const float GT  = 0.04905f;  // g * tau

    __shared__ float4 sW[2][WIN][32];   // w1c..w4c         W0 -> W1
    __shared__ float4 sS[2][WIN][32];   // spp,smm,sqn,wsum W1 -> W2
    __shared__ float  sT[4][WIN][32];   // Thr              W1 -> W4 (3-window hop)
    __shared__ float4 sH[2][WIN][32];   // hp,hq,hr,0       W2 -> W3
    __shared__ float4 sQ[2][WIN][32];   // pre-update q     W3 -> W4

    if (wid == 0) {
        // ================= Motors =================
        const float hover = g_hover;
        float w1 = hover, w2 = hover, w3 = hover, w4 = hover;
        float wd1 = 0.f, wd2 = 0.f, wd3 = 0.f, wd4 = 0.f;
        const float4* __restrict__ PM0 = g_pM0 + b;
        const float4* __restrict__ PM1 = g_pM1 + b;
        float4 bm0[WIN], bm1[WIN];
        #pragma unroll
        for (int j = 0; j < WIN; ++j) {
            bm0[j] = PM0[(size_t)j * B_DIM];
            bm1[j] = PM1[(size_t)j * B_DIM];
        }
        for (int p = 0; p < NWIN + 4; ++p) {
            if (p < NWIN) {
                const int s0  = p * WIN;
                const int par = p & 1;
                #pragma unroll
                for (int j = 0; j < WIN; ++j) {
                    const float4 c0 = bm0[j];   // C1..C4
                    const float4 c1 = bm1[j];   // A, mn, mx
                    float wdd1 = fmaf(c1.x, wd1, -w1) + c0.x;
                    float wdd2 = fmaf(c1.x, wd2, -w2) + c0.y;
                    float wdd3 = fmaf(c1.x, wd3, -w3) + c0.z;
                    float wdd4 = fmaf(c1.x, wd4, -w4) + c0.w;

                    float w1c = fminf(fmaxf(w1, c1.y), c1.z);
                    float w2c = fminf(fmaxf(w2, c1.y), c1.z);
                    float w3c = fminf(fmaxf(w3, c1.y), c1.z);
                    float w4c = fminf(fmaxf(w4, c1.y), c1.z);

                    sW[par][j][lane] = make_float4(w1c, w2c, w3c, w4c);

                    w1 = fmaf(tau, wd1, w1c);
                    w2 = fmaf(tau, wd2, w2c);
                    w3 = fmaf(tau, wd3, w3c);
                    w4 = fmaf(tau, wd4, w4c);
                    wd1 = fmaf(tau, wdd1, wd1);
                    wd2 = fmaf(tau, wdd2, wd2);
                    wd3 = fmaf(tau, wdd3, wd3);
                    wd4 = fmaf(tau, wdd4, wd4);

                    bm0[j] = PM0[(size_t)(s0 + WIN + j) * B_DIM];
                    bm1[j] = PM1[(size_t)(s0 + WIN + j) * B_DIM];
                }
            }
            BARRIER();
        }
    } else if (wid == 1) {
        // ================= Sums / Thr =================
        const float* __restrict__ PKT = g_kThz + b;
        float bk[WIN];
        #pragma unroll
        for (int j = 0; j < WIN; ++j) bk[j] = PKT[(size_t)j * B_DIM];
        for (int p = 0; p < NWIN + 4; ++p) {
            if (p >= 1 && p <= NWIN) {
                const int w    = p - 1;
                const int s0   = w * WIN;
                const int par  = w & 1;
                const int par4 = w & 3;
                float4 wv[WIN];
                #pragma unroll
                for (int j = 0; j < WIN; ++j) wv[j] = sW[par][j][lane];
                #pragma unroll
                for (int j = 0; j < WIN; ++j) {
                    const float4 wc = wv[j];
                    float s1 = wc.x * wc.x, s2 = wc.y * wc.y;
                    float s3 = wc.z * wc.z, s4 = wc.w * wc.w;
                    float a12 = s1 + s2, a34 = s3 + s4;
                    float d12 = s1 - s2, d34 = s3 - s4;
                    float sa  = a12 + a34;
                    float spp = a12 - a34;
                    float smm = d12 - d34;
                    float sqn = d12 + d34;
                    float wsum = (wc.x - wc.y) + (wc.z - wc.w);
                    float Thr = bk[j] * sa;

                    sS[par][j][lane]  = make_float4(spp, smm, sqn, wsum);
                    sT[par4][j][lane] = Thr;

                    bk[j] = PKT[(size_t)(s0 + WIN + j) * B_DIM];
                }
            }
            BARRIER();
        }
    } else if (wid == 2) {
        // ================= Body rates =================
        float pv = 0.f, qv = 0.f, rv = 0.f;
        const float4* __restrict__ PR0 = g_pR0 + b;
        const float4* __restrict__ PR1 = g_pR1 + b;
        float4 br0[WIN], br1[WIN];
        #pragma unroll
        for (int j = 0; j < WIN; ++j) {
            br0[j] = PR0[(size_t)j * B_DIM];
            br1[j] = PR1[(size_t)j * B_DIM];
        }
        for (int p = 0; p < NWIN + 4; ++p) {
            if (p >= 2 && p <= NWIN + 1) {
                const int w   = p - 2;
                const int s0  = w * WIN;
                const int par = w & 1;
                float4 m[WIN];
                #pragma unroll
                for (int j = 0; j < WIN; ++j) m[j] = sS[par][j][lane];
                #pragma unroll
                for (int j = 0; j < WIN; ++j) {
                    const float4 r0 = br0[j];   // e1, e2, -u1, u2
                    const float4 r1 = br1[j];   // kThd1, kThd2, e3, -kToz
                    const float4 mm = m[j];     // spp, smm, sqn, wsum

                    float qvrv = qv * rv, pvrv = pv * rv, pvqv = pv * qv;
                    float wq = mm.w * qv, wp = mm.w * pv;

                    float t1 = r0.x * qvrv;
                    t1 = fmaf(r0.z, wq, t1);
                    t1 = fmaf(r1.x, mm.y, t1);
                    float npv = pv + t1;

                    float t2 = r0.y * pvrv;
                    t2 = fmaf(r0.w, wp, t2);
                    t2 = fmaf(r1.y, mm.x, t2);
                    float nqv = qv + t2;

                    float t3 = r1.z * pvqv;
                    t3 = fmaf(r1.w, mm.z, t3);
                    float nrv = rv + t3;

                    // half-rates from CURRENT (pre-update) state
                    float hp = HT * pv, hq = HT * qv, hr = HT * rv;
                    sH[par][j][lane] = make_float4(hp, hq, hr, 0.f);

                    pv = npv; qv = nqv; rv = nrv;

                    br0[j] = PR0[(size_t)(s0 + WIN + j) * B_DIM];
                    br1[j] = PR1[(size_t)(s0 + WIN + j) * B_DIM];
                }
            }
            BARRIER();
        }
    } else if (wid == 3) {
        // ================= Quaternion =================
        float q0 = 1.f, q1 = 0.f, q2 = 0.f, q3 = 0.f;
        for (int p = 0; p < NWIN + 4; ++p) {
            if (p >= 3 && p <= NWIN + 2) {
                const int w   = p - 3;
                const int par = w & 1;
                float4 h[WIN];
                #pragma unroll
                for (int j = 0; j < WIN; ++j) h[j] = sH[par][j][lane];
                #pragma unroll
                for (int j = 0; j < WIN; ++j) {
                    const float hp = h[j].x, hq = h[j].y, hr = h[j].z;

                    // pre-update q goes to W4 (z-dynamics uses carry q)
                    sQ[par][j][lane] = make_float4(q0, q1, q2, q3);

                    float tA0 = fmaf(-hr, q3, fmaf(-hq, q2, (-hp) * q1));
                    float tA2 = fmaf(-hr, q1, fmaf( hq, q0,   hp  * q3));
                    float tB1 = fmaf( hr, q2, fmaf(-hq, q3,   hp  * q0));
                    float tB3 = fmaf( hr, q0, fmaf( hq, q1, (-hp) * q2));
                    float nq0 = q0 + tA0;
                    float nq2 = q2 + tA2;
                    float nq1 = q1 + tB1;
                    float nq3 = q3 + tB3;
                    q0 = nq0; q1 = nq1; q2 = nq2; q3 = nq3;
                }
            }
            BARRIER();
        }
    } else {
        // ================= z / loss =================
        float xz = 0.f, zd = 0.f;
        const float2* __restrict__ PQ = g_pQ + b;
        float2 bq[WIN];
        #pragma unroll
        for (int j = 0; j < WIN; ++j) bq[j] = PQ[(size_t)j * B_DIM];
        double acc;
        { float l0 = labels[b]; acc = (double)l0 * (double)l0; }
        for (int p = 0; p < NWIN + 4; ++p) {
            if (p >= 4) {
                const int w    = p - 4;
                const int s0   = w * WIN;
                const int par  = w & 1;
                const int par4 = w & 3;
                float4 qv4[WIN];
                float  thr[WIN];
                #pragma unroll
                for (int j = 0; j < WIN; ++j) {
                    qv4[j] = sQ[par][j][lane];
                    thr[j] = sT[par4][j][lane];
                }
                float accf = 0.f;
                #pragma unroll
                for (int j = 0; j < WIN; ++j) {
                    const float2 qc = bq[j];        // Cd', label
                    const float4 qd = qv4[j];
                    const float Thr = thr[j];

                    float sq0 = qd.x * qd.x, sq1 = qd.y * qd.y;
                    float sq2 = qd.z * qd.z, sq3 = qd.w * qd.w;
                    float qq = (sq0 - sq1) - (sq2 - sq3);

                    float zd2 = zd * zd;
                    float sz = (zd > 0.f) ? 1.f : ((zd < 0.f) ? -1.f : 0.f);
                    float drag = qc.x * (sz * zd2);
                    float nzd = zd + ((Thr * qq - drag) - GT);

                    float nxz_raw = fmaf(tau, nzd, xz);
                    float diff = nxz_raw - xz;
                    float nxz = (fabsf(diff) <= 400.0f) ? nxz_raw : xz;

                    float dz = nxz - qc.y;
                    if (s0 + j < NSTEP) accf = fmaf(dz, dz, accf);

                    xz = nxz; zd = nzd;

                    bq[j] = PQ[(size_t)(s0 + WIN + j) * B_DIM];
                }
                acc += (double)accf;
            }
            BARRIER();
        }
        g_loss[b] = acc;
    }
}

// ---------------------------------------------------------------------------
// Kernel 4: deterministic loss reduction -> mean
// ---------------------------------------------------------------------------
__global__ void loss_kernel(float* __restrict__ out)
{
    __shared__ double red[B_DIM];
    red[threadIdx.x] = g_loss[threadIdx.x];
    __syncthreads();
    #pragma unroll
    for (int s = 256; s > 0; s >>= 1) {
        if (threadIdx.x < s) red[threadIdx.x] += red[threadIdx.x + s];
        __syncthreads();
    }
    if (threadIdx.x == 0) out[0] = (float)(red[0] / (double)NELEM);
}

// ---------------------------------------------------------------------------
// Launch
// ---------------------------------------------------------------------------
extern "C" void kernel_launch(void* const* d_in, const int* in_sizes, int n_in,
                              void* d_out, int out_size)
{
    const float* labels = (const float*)d_in[0];
    const float* logits = (const float*)d_in[1];
    const float* u1     = (const float*)d_in[2];
    const float* u2     = (const float*)d_in[3];
    const float* u3     = (const float*)d_in[4];
    const float* u4     = (const float*)d_in[5];
    const float* maxM   = (const float*)d_in[6];
    const float* minM   = (const float*)d_in[7];

    prep_kernel<<<PREP_BLOCKS, 256>>>(logits, u1, u2, u3, u4, maxM, minM, labels);
    hover_kernel<<<1, 256>>>();
    sim_kernel<<<16, 160>>>(labels);
    loss_kernel<<<1, B_DIM>>>((float*)d_out);
}